// round 4
// baseline (speedup 1.0000x reference)
#include <cuda_runtime.h>
#include <math.h>

#define NNODES 100000
#define FIN    128
#define HID    256
#define NCLS   40
#define EMAX   1600000

// ---------------- scratch (device globals; no allocation allowed) ----------------
__device__ float g_bufA[(size_t)NNODES * HID];   // 102.4 MB
__device__ float g_bufB[(size_t)NNODES * HID];   // 102.4 MB
__device__ float g_dinv[NNODES];
__device__ int   g_hist[NNODES];
__device__ int   g_rowptr[NNODES + 1];
__device__ int   g_fill[NNODES];
__device__ int   g_col[EMAX];

__device__ __forceinline__ float* selbuf(int s) { return s ? g_bufB : g_bufA; }

// ---------------- precompute: degree, dinv, CSR by dst ----------------
__global__ void k_init() {
    int i = blockIdx.x * blockDim.x + threadIdx.x;
    if (i < NNODES) g_hist[i] = 0;
}

// edge_index is int32 (JAX x64 disabled): ei[0:E)=src, ei[E:2E)=dst
__global__ void k_hist(const int* __restrict__ ei, int E) {
    int e = blockIdx.x * blockDim.x + threadIdx.x;
    if (e < E) atomicAdd(&g_hist[ei[E + e]], 1);
}

__global__ void k_dinv() {
    int i = blockIdx.x * blockDim.x + threadIdx.x;
    if (i < NNODES) g_dinv[i] = rsqrtf((float)(g_hist[i] + 1)); // +1 self loop
}

// single-block exclusive scan of g_hist -> g_rowptr (and g_fill copy)
__global__ void k_scan(int n, int total_edges) {
    __shared__ int s[1024];
    const int t = threadIdx.x;
    const int C = (n + 1023) >> 10;
    const int lo = t * C;
    const int hi = (lo + C < n) ? lo + C : n;
    int sum = 0;
    for (int i = lo; i < hi; i++) sum += g_hist[i];
    s[t] = sum;
    __syncthreads();
    for (int off = 1; off < 1024; off <<= 1) {
        int v = (t >= off) ? s[t - off] : 0;
        __syncthreads();
        s[t] += v;
        __syncthreads();
    }
    int run = (t == 0) ? 0 : s[t - 1];
    for (int i = lo; i < hi; i++) {
        g_rowptr[i] = run;
        g_fill[i] = run;
        run += g_hist[i];
    }
    if (t == 1023) g_rowptr[n] = total_edges;
}

__global__ void k_scatter(const int* __restrict__ ei, int E) {
    int e = blockIdx.x * blockDim.x + threadIdx.x;
    if (e < E) {
        int d = ei[E + e];
        int pos = atomicAdd(&g_fill[d], 1);
        g_col[pos] = ei[e];
    }
}

// ---------------- aggregate: out[i] = dinv[i]*( sum_{s in N(i)} dinv[s]*in[s] + dinv[i]*in[i] ) ----------------
template <int F, bool BIAS, bool RELU>
__global__ void k_agg(const float* __restrict__ ext_in, int src_sel, int dst_sel,
                      const float* __restrict__ bias) {
    const float* in = (src_sel < 0) ? ext_in : selbuf(src_sel);
    float* out = selbuf(dst_sel);

    const int wid = (blockIdx.x * blockDim.x + threadIdx.x) >> 5;
    if (wid >= NNODES) return;
    const int lane = threadIdx.x & 31;
    constexpr int V = F / 128;  // float4 per lane
    float4 acc[V];
#pragma unroll
    for (int v = 0; v < V; v++) acc[v] = make_float4(0.f, 0.f, 0.f, 0.f);

    const int beg = g_rowptr[wid];
    const int end = g_rowptr[wid + 1];
    for (int base = beg; base < end; base += 32) {
        const int nrem = end - base;
        int idx = 0;
        float w = 0.f;
        if (lane < nrem) {
            idx = g_col[base + lane];
            w = g_dinv[idx];
        }
        const int m = nrem < 32 ? nrem : 32;
        for (int j = 0; j < m; j++) {
            const int s = __shfl_sync(0xffffffffu, idx, j);
            const float ww = __shfl_sync(0xffffffffu, w, j);
            const float4* row = reinterpret_cast<const float4*>(in + (size_t)s * F);
#pragma unroll
            for (int v = 0; v < V; v++) {
                float4 x = row[lane + v * 32];
                acc[v].x += ww * x.x;
                acc[v].y += ww * x.y;
                acc[v].z += ww * x.z;
                acc[v].w += ww * x.w;
            }
        }
    }
    const float di = g_dinv[wid];
    const float4* self = reinterpret_cast<const float4*>(in + (size_t)wid * F);
#pragma unroll
    for (int v = 0; v < V; v++) {
        float4 x = self[lane + v * 32];
        acc[v].x += di * x.x;
        acc[v].y += di * x.y;
        acc[v].z += di * x.z;
        acc[v].w += di * x.w;
    }
    float4* orow = reinterpret_cast<float4*>(out + (size_t)wid * F);
#pragma unroll
    for (int v = 0; v < V; v++) {
        float4 r;
        r.x = di * acc[v].x;
        r.y = di * acc[v].y;
        r.z = di * acc[v].z;
        r.w = di * acc[v].w;
        if (BIAS) {
            const int c = (lane + v * 32) * 4;
            r.x += bias[c + 0];
            r.y += bias[c + 1];
            r.z += bias[c + 2];
            r.w += bias[c + 3];
        }
        if (RELU) {
            r.x = fmaxf(r.x, 0.f);
            r.y = fmaxf(r.y, 0.f);
            r.z = fmaxf(r.z, 0.f);
            r.w = fmaxf(r.w, 0.f);
        }
        orow[lane + v * 32] = r;
    }
}

// aggregate F=40 + bias + log_softmax (final layer)
__global__ void k_agg40_lsm(int src_sel, float* __restrict__ out,
                            const float* __restrict__ bias) {
    const float* in = selbuf(src_sel);
    const int wid = (blockIdx.x * blockDim.x + threadIdx.x) >> 5;
    if (wid >= NNODES) return;
    const int lane = threadIdx.x & 31;
    const bool has2 = lane < (NCLS - 32);

    float a0 = 0.f, a1 = 0.f;
    const int beg = g_rowptr[wid];
    const int end = g_rowptr[wid + 1];
    for (int base = beg; base < end; base += 32) {
        const int nrem = end - base;
        int idx = 0;
        float w = 0.f;
        if (lane < nrem) {
            idx = g_col[base + lane];
            w = g_dinv[idx];
        }
        const int m = nrem < 32 ? nrem : 32;
        for (int j = 0; j < m; j++) {
            const int s = __shfl_sync(0xffffffffu, idx, j);
            const float ww = __shfl_sync(0xffffffffu, w, j);
            a0 += ww * in[(size_t)s * NCLS + lane];
            if (has2) a1 += ww * in[(size_t)s * NCLS + 32 + lane];
        }
    }
    const float di = g_dinv[wid];
    a0 += di * in[(size_t)wid * NCLS + lane];
    if (has2) a1 += di * in[(size_t)wid * NCLS + 32 + lane];

    a0 = di * a0 + bias[lane];
    a1 = has2 ? (di * a1 + bias[32 + lane]) : -INFINITY;

    float mx = fmaxf(a0, a1);
#pragma unroll
    for (int off = 16; off; off >>= 1) mx = fmaxf(mx, __shfl_xor_sync(0xffffffffu, mx, off));
    float se = expf(a0 - mx) + (has2 ? expf(a1 - mx) : 0.f);
#pragma unroll
    for (int off = 16; off; off >>= 1) se += __shfl_xor_sync(0xffffffffu, se, off);
    const float lse = logf(se) + mx;

    out[(size_t)wid * NCLS + lane] = a0 - lse;
    if (has2) out[(size_t)wid * NCLS + 32 + lane] = a1 - lse;
}

// ---------------- big fp32 GEMM: 128x128x16 tiles, 8x8 microtile, double-buffered ----------------
// C[M,256] = A[M,K] @ W[K,256]  (+bias+relu if EPI)
template <int K, int NOUT, bool EPI>
__global__ __launch_bounds__(256, 2) void k_gemm2(int src_sel, const float* __restrict__ W,
                                                  const float* __restrict__ bias, int dst_sel) {
    const float* A = selbuf(src_sel);
    float* C = selbuf(dst_sel);

    constexpr int BM = 128, BN = 128, BK = 16;
    constexpr int T = K / BK;
    __shared__ float As[2][BK][BM + 4];   // padded: transpose-store conflict-free
    __shared__ float Bs[2][BK][BN];

    const int tid = threadIdx.x;
    const int tx = tid & 15;    // col group (8 cols each)
    const int ty = tid >> 4;    // row group (8 rows each)
    const int m0 = blockIdx.x * BM;
    const int n0 = blockIdx.y * BN;

    // A-load mapping: lin in [0,512): row=lin>>2 (0..127), c4=lin&3 (4 float4 per row of 16 k)
    const int ar = (tid + 0) >> 1;        // 2 lin per thread: lin=tid*? -- use lin = tid + l*256
    (void)ar;

    float acc[8][8];
#pragma unroll
    for (int i = 0; i < 8; i++)
#pragma unroll
        for (int j = 0; j < 8; j++) acc[i][j] = 0.f;

    float4 ra[2], rb[2];

    auto load_regs = [&](int t) {
#pragma unroll
        for (int l = 0; l < 2; l++) {
            const int lin = tid + l * 256;
            const int r = lin >> 2;
            const int c4 = lin & 3;
            const int gr = m0 + r;
            ra[l] = make_float4(0.f, 0.f, 0.f, 0.f);
            if (gr < NNODES)
                ra[l] = *reinterpret_cast<const float4*>(A + (size_t)gr * K + t * BK + c4 * 4);
            const int br = lin >> 5;       // 0..15
            const int bc4 = lin & 31;      // 32 float4 per row of 128
            rb[l] = *reinterpret_cast<const float4*>(W + (size_t)(t * BK + br) * NOUT + n0 + bc4 * 4);
        }
    };
    auto store_smem = [&](int buf) {
#pragma unroll
        for (int l = 0; l < 2; l++) {
            const int lin = tid + l * 256;
            const int r = lin >> 2;
            const int c4 = lin & 3;
            As[buf][c4 * 4 + 0][r] = ra[l].x;
            As[buf][c4 * 4 + 1][r] = ra[l].y;
            As[buf][c4 * 4 + 2][r] = ra[l].z;
            As[buf][c4 * 4 + 3][r] = ra[l].w;
            const int br = lin >> 5;
            const int bc4 = lin & 31;
            *reinterpret_cast<float4*>(&Bs[buf][br][bc4 * 4]) = rb[l];
        }
    };

    load_regs(0);
    store_smem(0);
    __syncthreads();

    for (int t = 0; t < T; t++) {
        const int cur = t & 1;
        if (t + 1 < T) load_regs(t + 1);
#pragma unroll
        for (int kk = 0; kk < BK; kk++) {
            float a[8], b[8];
            *reinterpret_cast<float4*>(&a[0]) = *reinterpret_cast<const float4*>(&As[cur][kk][ty * 8]);
            *reinterpret_cast<float4*>(&a[4]) = *reinterpret_cast<const float4*>(&As[cur][kk][ty * 8 + 4]);
            *reinterpret_cast<float4*>(&b[0]) = *reinterpret_cast<const float4*>(&Bs[cur][kk][tx * 8]);
            *reinterpret_cast<float4*>(&b[4]) = *reinterpret_cast<const float4*>(&Bs[cur][kk][tx * 8 + 4]);
#pragma unroll
            for (int i = 0; i < 8; i++)
#pragma unroll
                for (int j = 0; j < 8; j++) acc[i][j] += a[i] * b[j];
        }
        if (t + 1 < T) {
            store_smem((t + 1) & 1);
            __syncthreads();
        }
    }

    // epilogue
    float bz[8];
#pragma unroll
    for (int j = 0; j < 8; j++) bz[j] = EPI ? bias[n0 + tx * 8 + j] : 0.f;
#pragma unroll
    for (int i = 0; i < 8; i++) {
        const int m = m0 + ty * 8 + i;
        if (m >= NNODES) continue;
        float4 r0, r1;
        r0.x = acc[i][0]; r0.y = acc[i][1]; r0.z = acc[i][2]; r0.w = acc[i][3];
        r1.x = acc[i][4]; r1.y = acc[i][5]; r1.z = acc[i][6]; r1.w = acc[i][7];
        if (EPI) {
            r0.x = fmaxf(r0.x + bz[0], 0.f); r0.y = fmaxf(r0.y + bz[1], 0.f);
            r0.z = fmaxf(r0.z + bz[2], 0.f); r0.w = fmaxf(r0.w + bz[3], 0.f);
            r1.x = fmaxf(r1.x + bz[4], 0.f); r1.y = fmaxf(r1.y + bz[5], 0.f);
            r1.z = fmaxf(r1.z + bz[6], 0.f); r1.w = fmaxf(r1.w + bz[7], 0.f);
        }
        float* crow = C + (size_t)m * NOUT + n0 + tx * 8;
        *reinterpret_cast<float4*>(crow) = r0;
        *reinterpret_cast<float4*>(crow + 4) = r1;
    }
}

// ---------------- small GEMM for NOUT=40 (kept from R3) ----------------
template <int K, int NOUT>
__global__ void k_gemm_small(int src_sel, const float* __restrict__ W, int dst_sel) {
    const float* A = selbuf(src_sel);
    float* C = selbuf(dst_sel);

    constexpr int BM = 128, BN = 64, BK = 32;
    __shared__ float As[BK][BM];
    __shared__ float Bs[BK][BN];
    const int tid = threadIdx.x;
    const int tx = tid & 15;
    const int ty = tid >> 4;
    const int m0 = blockIdx.x * BM;
    const int n0 = blockIdx.y * BN;

    float acc[8][4];
#pragma unroll
    for (int i = 0; i < 8; i++)
#pragma unroll
        for (int j = 0; j < 4; j++) acc[i][j] = 0.f;

    for (int k0 = 0; k0 < K; k0 += BK) {
#pragma unroll
        for (int l = 0; l < 4; l++) {
            const int lin = tid + l * 256;
            const int r = lin >> 3;
            const int c4 = lin & 7;
            float4 v = make_float4(0.f, 0.f, 0.f, 0.f);
            const int gr = m0 + r;
            if (gr < NNODES)
                v = *reinterpret_cast<const float4*>(A + (size_t)gr * K + k0 + c4 * 4);
            As[c4 * 4 + 0][r] = v.x;
            As[c4 * 4 + 1][r] = v.y;
            As[c4 * 4 + 2][r] = v.z;
            As[c4 * 4 + 3][r] = v.w;
        }
#pragma unroll
        for (int l = 0; l < 2; l++) {
            const int lin = tid + l * 256;
            const int r = lin >> 4;
            const int c4 = lin & 15;
            float4 v = make_float4(0.f, 0.f, 0.f, 0.f);
            const int gc = n0 + c4 * 4;
            if (gc < NOUT)
                v = *reinterpret_cast<const float4*>(W + (size_t)(k0 + r) * NOUT + gc);
            *reinterpret_cast<float4*>(&Bs[r][c4 * 4]) = v;
        }
        __syncthreads();
#pragma unroll
        for (int kk = 0; kk < BK; kk++) {
            float a[8];
#pragma unroll
            for (int i = 0; i < 8; i++) a[i] = As[kk][ty * 8 + i];
            const float4 b = *reinterpret_cast<const float4*>(&Bs[kk][tx * 4]);
            const float bb[4] = {b.x, b.y, b.z, b.w};
#pragma unroll
            for (int i = 0; i < 8; i++)
#pragma unroll
                for (int j = 0; j < 4; j++) acc[i][j] += a[i] * bb[j];
        }
        __syncthreads();
    }

#pragma unroll
    for (int i = 0; i < 8; i++) {
        const int m = m0 + ty * 8 + i;
        if (m >= NNODES) continue;
#pragma unroll
        for (int j = 0; j < 4; j++) {
            const int c = n0 + tx * 4 + j;
            if (c >= NOUT) continue;
            C[(size_t)m * NOUT + c] = acc[i][j];
        }
    }
}

// ---------------- launch ----------------
extern "C" void kernel_launch(void* const* d_in, const int* in_sizes, int n_in,
                              void* d_out, int out_size) {
    const float* x = (const float*)d_in[0];
    const int* ei = (const int*)d_in[1];   // int32 (JAX x64 disabled)
    const float* W1 = (const float*)d_in[2];
    const float* b1 = (const float*)d_in[3];
    const float* W2 = (const float*)d_in[4];
    const float* b2 = (const float*)d_in[5];
    const float* W3 = (const float*)d_in[6];
    const float* b3 = (const float*)d_in[7];
    const float* W4 = (const float*)d_in[8];
    const float* b4 = (const float*)d_in[9];
    float* out = (float*)d_out;
    const int E = in_sizes[1] / 2;

    // graph structure precompute
    k_init<<<(NNODES + 255) / 256, 256>>>();
    k_hist<<<(E + 255) / 256, 256>>>(ei, E);
    k_scan<<<1, 1024>>>(NNODES, E);
    k_dinv<<<(NNODES + 255) / 256, 256>>>();
    k_scatter<<<(E + 255) / 256, 256>>>(ei, E);

    const int AGG_BLOCKS = (NNODES + 7) / 8;  // 8 warps/block
    const dim3 G2((NNODES + 127) / 128, HID / 128);
    const dim3 G5((NNODES + 127) / 128, 1);

    // conv1: aggregate (F=128), then GEMM + bias + relu
    k_agg<128, false, false><<<AGG_BLOCKS, 256>>>(x, -1, 0, nullptr);        // x -> A
    k_gemm2<128, 256, true><<<G2, 256>>>(0, W1, b1, 1);                      // A -> B

    // conv2: GEMM, then aggregate + bias + relu
    k_gemm2<256, 256, false><<<G2, 256>>>(1, W2, nullptr, 0);                // B -> A
    k_agg<256, true, true><<<AGG_BLOCKS, 256>>>(nullptr, 0, 1, b2);          // A -> B

    // conv3 (reuses W2/b2)
    k_gemm2<256, 256, false><<<G2, 256>>>(1, W2, nullptr, 0);
    k_agg<256, true, true><<<AGG_BLOCKS, 256>>>(nullptr, 0, 1, b2);

    // conv4
    k_gemm2<256, 256, false><<<G2, 256>>>(1, W3, nullptr, 0);
    k_agg<256, true, true><<<AGG_BLOCKS, 256>>>(nullptr, 0, 1, b3);

    // conv5: GEMM to 40 classes, aggregate + bias + log_softmax
    k_gemm_small<256, 40><<<G5, 256>>>(1, W4, 0);
    k_agg40_lsm<<<AGG_BLOCKS, 256>>>(0, out, b4);
}